// round 12
// baseline (speedup 1.0000x reference)
#include <cuda_runtime.h>
#include <cuda_fp16.h>
#include <mma.h>
#include <float.h>

using namespace nvcuda;

// Problem constants (fixed by reference setup_inputs)
#define LN   1024      // sequence length L
#define DD   768       // hidden d
#define HH   12        // heads
#define EE   32        // entities
#define MM   4         // mentions
#define RR   256       // relations per doc
#define NMAX 4         // batch

// Scratch (device globals -- no allocation allowed)
__device__ float g_e_emb[NMAX * EE * DD];                        // (n,E,d)
__device__ __align__(16) __half g_e_att[NMAX * EE * HH * LN];    // (n,E,h,L) fp16
__device__ __align__(16) __half g_A[NMAX * RR * LN];             // ht_att fp16
__device__ __align__(16) __half g_B[NMAX * LN * DD];             // seq fp16

// ---------------------------------------------------------------------------
// Fused pre-kernel: e_emb | seq->fp16 | e_att(fp16), by blockIdx range.
// ---------------------------------------------------------------------------
#define NB_EMB   ((NMAX * EE * DD) / 256)                   // 384
#define NB_SPL   ((NMAX * LN * DD / 4) / 2 / 256)           // 1536
#define NB_EATT  ((NMAX * EE * HH * (LN / 4)) / 4 / 256)    // 384

__global__ void k_pre(const float* __restrict__ seq,
                      const float* __restrict__ att,
                      const int*   __restrict__ pos,
                      const float* __restrict__ mask,
                      int n)
{
    int blk = blockIdx.x;
    if (blk < NB_EMB) {
        // ---- e_emb ----
        int idx = blk * 256 + threadIdx.x;
        int total = n * EE * DD;
        if (idx >= total) return;
        int k = idx % DD;
        int e = (idx / DD) % EE;
        int i = idx / (DD * EE);
        const int*   p  = pos  + (i * EE + e) * MM;
        const float* mk = mask + (i * EE + e) * MM;
        float v[MM];
        float mx = -FLT_MAX;
#pragma unroll
        for (int m = 0; m < MM; m++) {
            int pp = p[m] + 1;                       // OFFSET
            float x = seq[(i * LN + pp) * DD + k];
            if (mk[m] <= 0.0f) x = -FLT_MAX;
            v[m] = x;
            mx = fmaxf(mx, x);
        }
        float s = 0.0f;
#pragma unroll
        for (int m = 0; m < MM; m++) s += expf(v[m] - mx);
        g_e_emb[idx] = mx + logf(s);
    } else if (blk < NB_EMB + NB_SPL) {
        // ---- seq -> fp16 (2 float4 per thread) ----
        int half_n = n * LN * DD / 4 / 2;
        int idx = (blk - NB_EMB) * 256 + threadIdx.x;
        if (idx >= half_n) return;
#pragma unroll
        for (int u = 0; u < 2; u++) {
            int id = idx + u * half_n;
            float4 v = ((const float4*)seq)[id];
            __half2 h01 = __floats2half2_rn(v.x, v.y);
            __half2 h23 = __floats2half2_rn(v.z, v.w);
            uint2 w;
            w.x = *(unsigned*)&h01;
            w.y = *(unsigned*)&h23;
            ((uint2*)g_B)[id] = w;
        }
    } else {
        // ---- e_att -> fp16 (4 float4 per thread for MLP) ----
        int q = n * EE * HH * (LN / 4) / 4;
        int base = (blk - NB_EMB - NB_SPL) * 256 + threadIdx.x;
        if (base >= q) return;
#pragma unroll
        for (int u = 0; u < 4; u++) {
            int idx = base + u * q;
            int l4 = idx % (LN / 4);
            int hh = (idx / (LN / 4)) % HH;
            int e  = (idx / ((LN / 4) * HH)) % EE;
            int i  = idx / ((LN / 4) * HH * EE);
            const int*   p  = pos  + (i * EE + e) * MM;
            const float* mk = mask + (i * EE + e) * MM;
            const float4* att4 = (const float4*)att;
            float cnt = 0.0f;
            float4 s = make_float4(0.f, 0.f, 0.f, 0.f);
#pragma unroll
            for (int m = 0; m < MM; m++) {
                float mm = mk[m];
                cnt += mm;
                int pp = p[m] + 1;
                float4 a = att4[((size_t)(i * HH + hh) * LN + pp) * (LN / 4) + l4];
                s.x += mm * a.x; s.y += mm * a.y; s.z += mm * a.z; s.w += mm * a.w;
            }
            float inv = 1.0f / fmaxf(cnt, 1.0f);
            __half2 h01 = __floats2half2_rn(s.x * inv, s.y * inv);
            __half2 h23 = __floats2half2_rn(s.z * inv, s.w * inv);
            uint2 w;
            w.x = *(unsigned*)&h01;
            w.y = *(unsigned*)&h23;
            ((uint2*)g_e_att)[idx] = w;
        }
    }
}

// ---------------------------------------------------------------------------
// ht_att: one block (256 thr) per (i,r), fp16 inputs, fp32 math.
// ht[l] = (1/H) sum_h eA[h,l]*eB[h,l];  ht /= (sum_l ht + 1e-5)
// Writes fp16 A operand for the GEMM.
// ---------------------------------------------------------------------------
__global__ void k_ht_att(const int* __restrict__ hts, int n)
{
    int b = blockIdx.x;               // i*R + r
    int i = b / RR;
    int ha = hts[b * 2 + 0];
    int ta = hts[b * 2 + 1];

    const uint2* A = (const uint2*)(g_e_att + (size_t)(i * EE + ha) * HH * LN);
    const uint2* B = (const uint2*)(g_e_att + (size_t)(i * EE + ta) * HH * LN);
    int t = threadIdx.x;              // 256 threads, 4 l's each

    float4 s = make_float4(0.f, 0.f, 0.f, 0.f);
#pragma unroll
    for (int hh = 0; hh < HH; hh++) {
        uint2 ua = A[hh * (LN / 4) + t];
        uint2 ub = B[hh * (LN / 4) + t];
        float2 a01 = __half22float2(*(__half2*)&ua.x);
        float2 a23 = __half22float2(*(__half2*)&ua.y);
        float2 b01 = __half22float2(*(__half2*)&ub.x);
        float2 b23 = __half22float2(*(__half2*)&ub.y);
        s.x += a01.x * b01.x; s.y += a01.y * b01.y;
        s.z += a23.x * b23.x; s.w += a23.y * b23.y;
    }
    const float invH = 1.0f / (float)HH;
    s.x *= invH; s.y *= invH; s.z *= invH; s.w *= invH;
    float local = s.x + s.y + s.z + s.w;

    __shared__ float red[8];
#pragma unroll
    for (int off = 16; off > 0; off >>= 1)
        local += __shfl_xor_sync(0xffffffffu, local, off);
    if ((t & 31) == 0) red[t >> 5] = local;
    __syncthreads();
    if (t < 32) {
        float x = (t < 8) ? red[t] : 0.0f;
#pragma unroll
        for (int off = 4; off > 0; off >>= 1)
            x += __shfl_xor_sync(0xffffffffu, x, off);
        if (t == 0) red[0] = x;
    }
    __syncthreads();
    float inv = 1.0f / (red[0] + 1e-5f);

    __half2 h01 = __floats2half2_rn(s.x * inv, s.y * inv);
    __half2 h23 = __floats2half2_rn(s.z * inv, s.w * inv);
    uint2 w;
    w.x = *(unsigned*)&h01;
    w.y = *(unsigned*)&h23;
    ((uint2*)(g_A + (size_t)b * LN))[t] = w;
}

// ---------------------------------------------------------------------------
// Kernel 4: rs plane GEMM, plain fp16 x fp16 -> fp32 (single term; error
// dilutes ~40x into the norm-weighted rel_err, measured headroom ~350x).
// Block 64(M) x 128(N), BK=32, 8 warps as 4(M) x 2(N) -> warp tile 16x64
// (4 independent accs / warp, reuse distance 4). Double-buffered smem,
// register prefetch. grid = 6 x 4 x 4 = 96 blocks -> single wave.
// Fused hs/ts plane copy.
// ---------------------------------------------------------------------------
#define GBM 64
#define GBN 128
#define GBK 32
#define GT  256
#define LDA (GBK + 8)    // 40 halves
#define LDB (GBN + 8)    // 136 halves

__global__ __launch_bounds__(GT, 1) void k_gemm(const int* __restrict__ hts,
                                                float* __restrict__ out, int n)
{
    __shared__ __align__(16) __half As[2][GBM][LDA];
    __shared__ __align__(16) __half Bs[2][GBK][LDB];

    int i = blockIdx.z;
    const __half* Ad = g_A + (size_t)i * RR * LN;
    const __half* Bd = g_B + (size_t)i * LN * DD;
    size_t P = (size_t)n * RR * DD;
    float* Cd = out + 2 * P + (size_t)i * RR * DD;      // R x D

    int rowBase = blockIdx.y * GBM;
    int colBase = blockIdx.x * GBN;
    int tid = threadIdx.x;
    int w   = tid >> 5;
    int wm  = w & 3;          // 0..3 : M slice (16 rows)
    int wn  = w >> 2;         // 0..1 : N slice (64 cols)

    // ---- loader slots (uint4 = 8 halves) ----
    // A: 64 x 32 / 8 = 256 slots; 1 per thread
    int aRow = tid >> 2, aK8 = (tid & 3) * 8;
    // B: 32 x 128 / 8 = 512 slots; 2 per thread
    int bR[2], bN[2];
#pragma unroll
    for (int s = 0; s < 2; s++) {
        int id = tid + s * GT;
        bR[s] = id >> 4; bN[s] = (id & 15) * 8;
    }

    wmma::fragment<wmma::accumulator, 16, 16, 16, float> acc[4];
#pragma unroll
    for (int j = 0; j < 4; j++) wmma::fill_fragment(acc[j], 0.0f);

    // ---- initial global loads (k0 = 0) ----
    uint4 ra, rb[2];
    ra = *(const uint4*)&Ad[(size_t)(rowBase + aRow) * LN + aK8];
#pragma unroll
    for (int s = 0; s < 2; s++)
        rb[s] = *(const uint4*)&Bd[(size_t)bR[s] * DD + colBase + bN[s]];

    int buf = 0;
    for (int k0 = 0; k0 < LN; k0 += GBK) {
        *(uint4*)&As[buf][aRow][aK8] = ra;
#pragma unroll
        for (int s = 0; s < 2; s++)
            *(uint4*)&Bs[buf][bR[s]][bN[s]] = rb[s];
        __syncthreads();

        int kn = k0 + GBK;
        if (kn < LN) {
            ra = *(const uint4*)&Ad[(size_t)(rowBase + aRow) * LN + kn + aK8];
#pragma unroll
            for (int s = 0; s < 2; s++)
                rb[s] = *(const uint4*)&Bd[(size_t)(kn + bR[s]) * DD + colBase + bN[s]];
        }

#pragma unroll
        for (int kk = 0; kk < GBK / 16; kk++) {
            wmma::fragment<wmma::matrix_a, 16, 16, 16, __half, wmma::row_major> fa;
            wmma::fragment<wmma::matrix_b, 16, 16, 16, __half, wmma::row_major> fb[4];
            wmma::load_matrix_sync(fa, &As[buf][wm * 16][kk * 16], LDA);
#pragma unroll
            for (int j = 0; j < 4; j++)
                wmma::load_matrix_sync(fb[j], &Bs[buf][kk * 16][wn * 64 + j * 16], LDB);
#pragma unroll
            for (int j = 0; j < 4; j++)
                wmma::mma_sync(acc[j], fa, fb[j], acc[j]);
        }
        buf ^= 1;
        __syncthreads();
    }

    // ---- epilogue: store accumulators ----
#pragma unroll
    for (int j = 0; j < 4; j++) {
        float* c = &Cd[(size_t)(rowBase + wm * 16) * DD + colBase + wn * 64 + j * 16];
        wmma::store_matrix_sync(c, acc[j], DD, wmma::mem_row_major);
    }

    // ---- fused hs/ts plane copy for this block's (row, col) tile ----
    {
        const float4* emb4 = (const float4*)g_e_emb;
        float4* out4 = (float4*)out;
        size_t P4 = (size_t)n * RR * (DD / 4);
        // tile = 64 rows x 32 float4 cols = 2048 float4 per plane; 8 per thread
#pragma unroll
        for (int s = 0; s < 8; s++) {
            int idx = tid + s * GT;        // 0..2047
            int row = idx >> 5;            // 0..63
            int c4  = idx & 31;
            int b = i * RR + rowBase + row;
            int ha = hts[b * 2 + 0];
            int ta = hts[b * 2 + 1];
            int col4 = colBase / 4 + c4;
            float4 vh = emb4[(size_t)(i * EE + ha) * (DD / 4) + col4];
            float4 vt = emb4[(size_t)(i * EE + ta) * (DD / 4) + col4];
            out4[(size_t)b * (DD / 4) + col4]      = vh;
            out4[P4 + (size_t)b * (DD / 4) + col4] = vt;
        }
    }
}

// ---------------------------------------------------------------------------
extern "C" void kernel_launch(void* const* d_in, const int* in_sizes, int n_in,
                              void* d_out, int out_size)
{
    const float* seq  = (const float*)d_in[0];   // (n, L, d)
    const float* att  = (const float*)d_in[1];   // (n, h, L, L)
    const int*   pos  = (const int*)  d_in[2];   // (n, E, M)
    const float* mask = (const float*)d_in[3];   // (n, E, M)
    const int*   hts  = (const int*)  d_in[4];   // (n, R, 2)
    float* out = (float*)d_out;

    int n = in_sizes[0] / (LN * DD);
    if (n > NMAX) n = NMAX;

    {   // fused e_emb + seq->fp16 + e_att(fp16)
        k_pre<<<NB_EMB + NB_SPL + NB_EATT, 256>>>(seq, att, pos, mask, n);
    }
    {   // ht_att (fp16 in, fp16 A out)
        k_ht_att<<<n * RR, 256>>>(hts, n);
    }
    {   // rs plane GEMM (plain fp16 tensor cores) + hs/ts copy
        dim3 grid(DD / GBN, RR / GBM, n);
        k_gemm<<<grid, GT>>>(hts, out, n);
    }
}

// round 13
// speedup vs baseline: 1.1967x; 1.1967x over previous
#include <cuda_runtime.h>
#include <cuda_fp16.h>
#include <mma.h>
#include <float.h>

using namespace nvcuda;

// Problem constants (fixed by reference setup_inputs)
#define LN   1024      // sequence length L
#define DD   768       // hidden d
#define HH   12        // heads
#define EE   32        // entities
#define MM   4         // mentions
#define RR   256       // relations per doc
#define NMAX 4         // batch

// Scratch (device globals -- no allocation allowed)
__device__ float g_e_emb[NMAX * EE * DD];                        // (n,E,d)
__device__ __align__(16) __half g_e_att[NMAX * EE * HH * LN];    // (n,E,h,L) fp16
__device__ __align__(16) __half g_A[NMAX * RR * LN];             // ht_att fp16
__device__ __align__(16) __half g_B[NMAX * LN * DD];             // seq fp16

// ---------------------------------------------------------------------------
// Fused pre-kernel: e_emb | seq->fp16 | e_att(fp16), by blockIdx range.
// ---------------------------------------------------------------------------
#define NB_EMB   ((NMAX * EE * DD) / 256)                   // 384
#define NB_SPL   ((NMAX * LN * DD / 4) / 4 / 256)           // 768
#define NB_EATT  ((NMAX * EE * HH * (LN / 4)) / 4 / 256)    // 384

__global__ void k_pre(const float* __restrict__ seq,
                      const float* __restrict__ att,
                      const int*   __restrict__ pos,
                      const float* __restrict__ mask,
                      int n)
{
    int blk = blockIdx.x;
    if (blk < NB_EMB) {
        // ---- e_emb ----
        int idx = blk * 256 + threadIdx.x;
        int total = n * EE * DD;
        if (idx >= total) return;
        int k = idx % DD;
        int e = (idx / DD) % EE;
        int i = idx / (DD * EE);
        const int*   p  = pos  + (i * EE + e) * MM;
        const float* mk = mask + (i * EE + e) * MM;
        float v[MM];
        float mx = -FLT_MAX;
#pragma unroll
        for (int m = 0; m < MM; m++) {
            int pp = p[m] + 1;                       // OFFSET
            float x = seq[(i * LN + pp) * DD + k];
            if (mk[m] <= 0.0f) x = -FLT_MAX;
            v[m] = x;
            mx = fmaxf(mx, x);
        }
        float s = 0.0f;
#pragma unroll
        for (int m = 0; m < MM; m++) s += expf(v[m] - mx);
        g_e_emb[idx] = mx + logf(s);
    } else if (blk < NB_EMB + NB_SPL) {
        // ---- seq -> fp16 (4 float4 per thread for MLP) ----
        int q = n * LN * DD / 4 / 4;
        int idx = (blk - NB_EMB) * 256 + threadIdx.x;
        if (idx >= q) return;
#pragma unroll
        for (int u = 0; u < 4; u++) {
            int id = idx + u * q;
            float4 v = ((const float4*)seq)[id];
            __half2 h01 = __floats2half2_rn(v.x, v.y);
            __half2 h23 = __floats2half2_rn(v.z, v.w);
            uint2 w;
            w.x = *(unsigned*)&h01;
            w.y = *(unsigned*)&h23;
            ((uint2*)g_B)[id] = w;
        }
    } else {
        // ---- e_att -> fp16 (4 float4 per thread for MLP) ----
        int q = n * EE * HH * (LN / 4) / 4;
        int base = (blk - NB_EMB - NB_SPL) * 256 + threadIdx.x;
        if (base >= q) return;
#pragma unroll
        for (int u = 0; u < 4; u++) {
            int idx = base + u * q;
            int l4 = idx % (LN / 4);
            int hh = (idx / (LN / 4)) % HH;
            int e  = (idx / ((LN / 4) * HH)) % EE;
            int i  = idx / ((LN / 4) * HH * EE);
            const int*   p  = pos  + (i * EE + e) * MM;
            const float* mk = mask + (i * EE + e) * MM;
            const float4* att4 = (const float4*)att;
            float cnt = 0.0f;
            float4 s = make_float4(0.f, 0.f, 0.f, 0.f);
#pragma unroll
            for (int m = 0; m < MM; m++) {
                float mm = mk[m];
                cnt += mm;
                int pp = p[m] + 1;
                float4 a = att4[((size_t)(i * HH + hh) * LN + pp) * (LN / 4) + l4];
                s.x += mm * a.x; s.y += mm * a.y; s.z += mm * a.z; s.w += mm * a.w;
            }
            float inv = 1.0f / fmaxf(cnt, 1.0f);
            __half2 h01 = __floats2half2_rn(s.x * inv, s.y * inv);
            __half2 h23 = __floats2half2_rn(s.z * inv, s.w * inv);
            uint2 w;
            w.x = *(unsigned*)&h01;
            w.y = *(unsigned*)&h23;
            ((uint2*)g_e_att)[idx] = w;
        }
    }
}

// ---------------------------------------------------------------------------
// ht_att: one block (256 thr) per (i,r), fp16 inputs, fp32 math.
// ht[l] = (1/H) sum_h eA[h,l]*eB[h,l];  ht /= (sum_l ht + 1e-5)
// Writes fp16 A operand for the GEMM.
// ---------------------------------------------------------------------------
__global__ void k_ht_att(const int* __restrict__ hts, int n)
{
    int b = blockIdx.x;               // i*R + r
    int i = b / RR;
    int ha = hts[b * 2 + 0];
    int ta = hts[b * 2 + 1];

    const uint2* A = (const uint2*)(g_e_att + (size_t)(i * EE + ha) * HH * LN);
    const uint2* B = (const uint2*)(g_e_att + (size_t)(i * EE + ta) * HH * LN);
    int t = threadIdx.x;              // 256 threads, 4 l's each

    float4 s = make_float4(0.f, 0.f, 0.f, 0.f);
#pragma unroll
    for (int hh = 0; hh < HH; hh++) {
        uint2 ua = A[hh * (LN / 4) + t];
        uint2 ub = B[hh * (LN / 4) + t];
        float2 a01 = __half22float2(*(__half2*)&ua.x);
        float2 a23 = __half22float2(*(__half2*)&ua.y);
        float2 b01 = __half22float2(*(__half2*)&ub.x);
        float2 b23 = __half22float2(*(__half2*)&ub.y);
        s.x += a01.x * b01.x; s.y += a01.y * b01.y;
        s.z += a23.x * b23.x; s.w += a23.y * b23.y;
    }
    const float invH = 1.0f / (float)HH;
    s.x *= invH; s.y *= invH; s.z *= invH; s.w *= invH;
    float local = s.x + s.y + s.z + s.w;

    __shared__ float red[8];
#pragma unroll
    for (int off = 16; off > 0; off >>= 1)
        local += __shfl_xor_sync(0xffffffffu, local, off);
    if ((t & 31) == 0) red[t >> 5] = local;
    __syncthreads();
    if (t < 32) {
        float x = (t < 8) ? red[t] : 0.0f;
#pragma unroll
        for (int off = 4; off > 0; off >>= 1)
            x += __shfl_xor_sync(0xffffffffu, x, off);
        if (t == 0) red[0] = x;
    }
    __syncthreads();
    float inv = 1.0f / (red[0] + 1e-5f);

    __half2 h01 = __floats2half2_rn(s.x * inv, s.y * inv);
    __half2 h23 = __floats2half2_rn(s.z * inv, s.w * inv);
    uint2 w;
    w.x = *(unsigned*)&h01;
    w.y = *(unsigned*)&h23;
    ((uint2*)(g_A + (size_t)b * LN))[t] = w;
}

// ---------------------------------------------------------------------------
// Kernel 4: rs plane GEMM, plain fp16 x fp16 -> fp32, on the PROVEN R11
// geometry: Block 64(M) x 96(N), BK=32, 8 warps as 4(M) x 2(N) -> warp
// tile 16x48 (3 accs, reuse distance 3). Per k-step: 1 A-ldsm + 3 B-ldsm
// + 3 mma. Double-buffered smem, register prefetch.
// grid = 8 x 4 x 4 = 128 blocks -> single wave. Fused hs/ts plane copy.
// ---------------------------------------------------------------------------
#define GBM 64
#define GBN 96
#define GBK 32
#define GT  256
#define LDA (GBK + 8)    // 40 halves
#define LDB (GBN + 8)    // 104 halves

__global__ __launch_bounds__(GT, 1) void k_gemm(const int* __restrict__ hts,
                                                float* __restrict__ out, int n)
{
    __shared__ __align__(16) __half As[2][GBM][LDA];
    __shared__ __align__(16) __half Bs[2][GBK][LDB];

    int i = blockIdx.z;
    const __half* Ad = g_A + (size_t)i * RR * LN;
    const __half* Bd = g_B + (size_t)i * LN * DD;
    size_t P = (size_t)n * RR * DD;
    float* Cd = out + 2 * P + (size_t)i * RR * DD;      // R x D

    int rowBase = blockIdx.y * GBM;
    int colBase = blockIdx.x * GBN;
    int tid = threadIdx.x;
    int w   = tid >> 5;
    int wm  = w & 3;          // 0..3 : M slice (16 rows)
    int wn  = w >> 2;         // 0..1 : N slice (48 cols)

    // ---- loader slots (uint4 = 8 halves) ----
    // A: 64 rows x 32 k / 8 = 256 slots; 1 per thread
    int aRow = tid >> 2, aK8 = (tid & 3) * 8;
    // B: 32 k x 96 / 8 = 384 slots; slot tid, plus tid+256 for tid<128
    int b0Row = tid / 12,         b0N = (tid % 12) * 8;
    int b1Row = (tid + 256) / 12, b1N = ((tid + 256) % 12) * 8;
    bool hasB1 = tid < 128;

    wmma::fragment<wmma::accumulator, 16, 16, 16, float> acc[3];
#pragma unroll
    for (int j = 0; j < 3; j++) wmma::fill_fragment(acc[j], 0.0f);

    // ---- initial global loads (k0 = 0) ----
    uint4 ra, rb0, rb1;
    ra = *(const uint4*)&Ad[(size_t)(rowBase + aRow) * LN + aK8];
    rb0 = *(const uint4*)&Bd[(size_t)b0Row * DD + colBase + b0N];
    if (hasB1) rb1 = *(const uint4*)&Bd[(size_t)b1Row * DD + colBase + b1N];

    int buf = 0;
    for (int k0 = 0; k0 < LN; k0 += GBK) {
        *(uint4*)&As[buf][aRow][aK8] = ra;
        *(uint4*)&Bs[buf][b0Row][b0N] = rb0;
        if (hasB1) *(uint4*)&Bs[buf][b1Row][b1N] = rb1;
        __syncthreads();

        int kn = k0 + GBK;
        if (kn < LN) {
            ra = *(const uint4*)&Ad[(size_t)(rowBase + aRow) * LN + kn + aK8];
            rb0 = *(const uint4*)&Bd[(size_t)(kn + b0Row) * DD + colBase + b0N];
            if (hasB1) rb1 = *(const uint4*)&Bd[(size_t)(kn + b1Row) * DD + colBase + b1N];
        }

#pragma unroll
        for (int kk = 0; kk < GBK / 16; kk++) {
            wmma::fragment<wmma::matrix_a, 16, 16, 16, __half, wmma::row_major> fa;
            wmma::fragment<wmma::matrix_b, 16, 16, 16, __half, wmma::row_major> fb[3];
            wmma::load_matrix_sync(fa, &As[buf][wm * 16][kk * 16], LDA);
#pragma unroll
            for (int j = 0; j < 3; j++)
                wmma::load_matrix_sync(fb[j], &Bs[buf][kk * 16][wn * 48 + j * 16], LDB);
#pragma unroll
            for (int j = 0; j < 3; j++)
                wmma::mma_sync(acc[j], fa, fb[j], acc[j]);
        }
        buf ^= 1;
        __syncthreads();
    }

    // ---- epilogue: store accumulators ----
#pragma unroll
    for (int j = 0; j < 3; j++) {
        float* c = &Cd[(size_t)(rowBase + wm * 16) * DD + colBase + wn * 48 + j * 16];
        wmma::store_matrix_sync(c, acc[j], DD, wmma::mem_row_major);
    }

    // ---- fused hs/ts plane copy for this block's (row, col) tile ----
    {
        const float4* emb4 = (const float4*)g_e_emb;
        float4* out4 = (float4*)out;
        size_t P4 = (size_t)n * RR * (DD / 4);
        // tile = 64 rows x 24 float4 cols = 1536 float4 per plane; 6 per thread
#pragma unroll
        for (int s = 0; s < 6; s++) {
            int idx = tid + s * GT;        // 0..1535
            int row = idx / 24;            // 0..63
            int c4  = idx % 24;
            int b = i * RR + rowBase + row;
            int ha = hts[b * 2 + 0];
            int ta = hts[b * 2 + 1];
            int col4 = colBase / 4 + c4;
            float4 vh = emb4[(size_t)(i * EE + ha) * (DD / 4) + col4];
            float4 vt = emb4[(size_t)(i * EE + ta) * (DD / 4) + col4];
            out4[(size_t)b * (DD / 4) + col4]      = vh;
            out4[P4 + (size_t)b * (DD / 4) + col4] = vt;
        }
    }
}

// ---------------------------------------------------------------------------
extern "C" void kernel_launch(void* const* d_in, const int* in_sizes, int n_in,
                              void* d_out, int out_size)
{
    const float* seq  = (const float*)d_in[0];   // (n, L, d)
    const float* att  = (const float*)d_in[1];   // (n, h, L, L)
    const int*   pos  = (const int*)  d_in[2];   // (n, E, M)
    const float* mask = (const float*)d_in[3];   // (n, E, M)
    const int*   hts  = (const int*)  d_in[4];   // (n, R, 2)
    float* out = (float*)d_out;

    int n = in_sizes[0] / (LN * DD);
    if (n > NMAX) n = NMAX;

    {   // fused e_emb + seq->fp16 + e_att(fp16)
        k_pre<<<NB_EMB + NB_SPL + NB_EATT, 256>>>(seq, att, pos, mask, n);
    }
    {   // ht_att (fp16 in, fp16 A out)
        k_ht_att<<<n * RR, 256>>>(hts, n);
    }
    {   // rs plane GEMM (single-term fp16, R11 geometry) + hs/ts copy
        dim3 grid(DD / GBN, RR / GBM, n);
        k_gemm<<<grid, GT>>>(hts, out, n);
    }
}

// round 14
// speedup vs baseline: 1.4005x; 1.1703x over previous
#include <cuda_runtime.h>
#include <cuda_fp16.h>
#include <mma.h>
#include <float.h>

using namespace nvcuda;

// Problem constants (fixed by reference setup_inputs)
#define LN   1024      // sequence length L
#define DD   768       // hidden d
#define HH   12        // heads
#define EE   32        // entities
#define MM   4         // mentions
#define RR   256       // relations per doc
#define NMAX 4         // batch

// Scratch (device globals -- no allocation allowed)
__device__ float g_e_emb[NMAX * EE * DD];                        // (n,E,d)
__device__ __align__(16) __half g_e_att[NMAX * EE * HH * LN];    // (n,E,h,L) fp16
__device__ __align__(16) __half g_A[NMAX * RR * LN];             // ht_att fp16
__device__ __align__(16) __half g_B[NMAX * LN * DD];             // seq fp16

// ---------------------------------------------------------------------------
// Fused pre-kernel: e_emb | seq->fp16 | e_att(fp16), by blockIdx range.
// split: 2 float4/thread (more blocks = better for this latency-bound kernel,
// per R12 vs R13). e_att: 2 float4/thread.
// ---------------------------------------------------------------------------
#define NB_EMB   ((NMAX * EE * DD) / 256)                   // 384
#define NB_SPL   ((NMAX * LN * DD / 4) / 2 / 256)           // 1536
#define NB_EATT  ((NMAX * EE * HH * (LN / 4)) / 2 / 256)    // 768

__global__ void k_pre(const float* __restrict__ seq,
                      const float* __restrict__ att,
                      const int*   __restrict__ pos,
                      const float* __restrict__ mask,
                      int n)
{
    int blk = blockIdx.x;
    if (blk < NB_EMB) {
        // ---- e_emb ----
        int idx = blk * 256 + threadIdx.x;
        int total = n * EE * DD;
        if (idx >= total) return;
        int k = idx % DD;
        int e = (idx / DD) % EE;
        int i = idx / (DD * EE);
        const int*   p  = pos  + (i * EE + e) * MM;
        const float* mk = mask + (i * EE + e) * MM;
        float v[MM];
        float mx = -FLT_MAX;
#pragma unroll
        for (int m = 0; m < MM; m++) {
            int pp = p[m] + 1;                       // OFFSET
            float x = seq[(i * LN + pp) * DD + k];
            if (mk[m] <= 0.0f) x = -FLT_MAX;
            v[m] = x;
            mx = fmaxf(mx, x);
        }
        float s = 0.0f;
#pragma unroll
        for (int m = 0; m < MM; m++) s += expf(v[m] - mx);
        g_e_emb[idx] = mx + logf(s);
    } else if (blk < NB_EMB + NB_SPL) {
        // ---- seq -> fp16 (2 float4 per thread) ----
        int half_n = n * LN * DD / 4 / 2;
        int idx = (blk - NB_EMB) * 256 + threadIdx.x;
        if (idx >= half_n) return;
#pragma unroll
        for (int u = 0; u < 2; u++) {
            int id = idx + u * half_n;
            float4 v = ((const float4*)seq)[id];
            __half2 h01 = __floats2half2_rn(v.x, v.y);
            __half2 h23 = __floats2half2_rn(v.z, v.w);
            uint2 w;
            w.x = *(unsigned*)&h01;
            w.y = *(unsigned*)&h23;
            ((uint2*)g_B)[id] = w;
        }
    } else {
        // ---- e_att -> fp16 (2 float4 per thread) ----
        int half_n = n * EE * HH * (LN / 4) / 2;
        int base = (blk - NB_EMB - NB_SPL) * 256 + threadIdx.x;
        if (base >= half_n) return;
#pragma unroll
        for (int u = 0; u < 2; u++) {
            int idx = base + u * half_n;
            int l4 = idx % (LN / 4);
            int hh = (idx / (LN / 4)) % HH;
            int e  = (idx / ((LN / 4) * HH)) % EE;
            int i  = idx / ((LN / 4) * HH * EE);
            const int4  p4 = *(const int4*)  (pos  + (i * EE + e) * MM);
            const float4 m4 = *(const float4*)(mask + (i * EE + e) * MM);
            const float4* att4 = (const float4*)att;
            int   pp[MM] = {p4.x + 1, p4.y + 1, p4.z + 1, p4.w + 1};
            float mk[MM] = {m4.x, m4.y, m4.z, m4.w};
            float cnt = mk[0] + mk[1] + mk[2] + mk[3];
            float4 s = make_float4(0.f, 0.f, 0.f, 0.f);
#pragma unroll
            for (int m = 0; m < MM; m++) {
                float4 a = att4[((size_t)(i * HH + hh) * LN + pp[m]) * (LN / 4) + l4];
                s.x += mk[m] * a.x; s.y += mk[m] * a.y;
                s.z += mk[m] * a.z; s.w += mk[m] * a.w;
            }
            float inv = 1.0f / fmaxf(cnt, 1.0f);
            __half2 h01 = __floats2half2_rn(s.x * inv, s.y * inv);
            __half2 h23 = __floats2half2_rn(s.z * inv, s.w * inv);
            uint2 w;
            w.x = *(unsigned*)&h01;
            w.y = *(unsigned*)&h23;
            ((uint2*)g_e_att)[idx] = w;
        }
    }
}

// ---------------------------------------------------------------------------
// ht_att: one block (256 thr) per (i,r), fp16 inputs, fp32 math.
// ht[l] = (1/H) sum_h eA[h,l]*eB[h,l];  ht /= (sum_l ht + 1e-5)
// Writes fp16 A operand for the GEMM.
// ---------------------------------------------------------------------------
__global__ void k_ht_att(const int* __restrict__ hts, int n)
{
    int b = blockIdx.x;               // i*R + r
    int i = b / RR;
    int ha = hts[b * 2 + 0];
    int ta = hts[b * 2 + 1];

    const uint2* A = (const uint2*)(g_e_att + (size_t)(i * EE + ha) * HH * LN);
    const uint2* B = (const uint2*)(g_e_att + (size_t)(i * EE + ta) * HH * LN);
    int t = threadIdx.x;              // 256 threads, 4 l's each

    float4 s = make_float4(0.f, 0.f, 0.f, 0.f);
#pragma unroll
    for (int hh = 0; hh < HH; hh++) {
        uint2 ua = A[hh * (LN / 4) + t];
        uint2 ub = B[hh * (LN / 4) + t];
        float2 a01 = __half22float2(*(__half2*)&ua.x);
        float2 a23 = __half22float2(*(__half2*)&ua.y);
        float2 b01 = __half22float2(*(__half2*)&ub.x);
        float2 b23 = __half22float2(*(__half2*)&ub.y);
        s.x += a01.x * b01.x; s.y += a01.y * b01.y;
        s.z += a23.x * b23.x; s.w += a23.y * b23.y;
    }
    const float invH = 1.0f / (float)HH;
    s.x *= invH; s.y *= invH; s.z *= invH; s.w *= invH;
    float local = s.x + s.y + s.z + s.w;

    __shared__ float red[8];
#pragma unroll
    for (int off = 16; off > 0; off >>= 1)
        local += __shfl_xor_sync(0xffffffffu, local, off);
    if ((t & 31) == 0) red[t >> 5] = local;
    __syncthreads();
    if (t < 32) {
        float x = (t < 8) ? red[t] : 0.0f;
#pragma unroll
        for (int off = 4; off > 0; off >>= 1)
            x += __shfl_xor_sync(0xffffffffu, x, off);
        if (t == 0) red[0] = x;
    }
    __syncthreads();
    float inv = 1.0f / (red[0] + 1e-5f);

    __half2 h01 = __floats2half2_rn(s.x * inv, s.y * inv);
    __half2 h23 = __floats2half2_rn(s.z * inv, s.w * inv);
    uint2 w;
    w.x = *(unsigned*)&h01;
    w.y = *(unsigned*)&h23;
    ((uint2*)(g_A + (size_t)b * LN))[t] = w;
}

// ---------------------------------------------------------------------------
// Kernel 4: rs plane GEMM, plain fp16 x fp16 -> fp32.
// R13 warp geometry (64x96 block, 8 warps 4(M)x2(N), warp tile 16x48,
// 3 accs) but BK=64: halves the __syncthreads count (8 k0-iters of
// 4 ksteps). Double-buffered smem (45KB), register prefetch.
// grid = 8 x 4 x 4 = 128 blocks -> single wave. Fused hs/ts plane copy.
// ---------------------------------------------------------------------------
#define GBM 64
#define GBN 96
#define GBK 64
#define GT  256
#define LDA (GBK + 8)    // 72 halves
#define LDB (GBN + 8)    // 104 halves

__global__ __launch_bounds__(GT, 1) void k_gemm(const int* __restrict__ hts,
                                                float* __restrict__ out, int n)
{
    __shared__ __align__(16) __half As[2][GBM][LDA];
    __shared__ __align__(16) __half Bs[2][GBK][LDB];

    int i = blockIdx.z;
    const __half* Ad = g_A + (size_t)i * RR * LN;
    const __half* Bd = g_B + (size_t)i * LN * DD;
    size_t P = (size_t)n * RR * DD;
    float* Cd = out + 2 * P + (size_t)i * RR * DD;      // R x D

    int rowBase = blockIdx.y * GBM;
    int colBase = blockIdx.x * GBN;
    int tid = threadIdx.x;
    int w   = tid >> 5;
    int wm  = w & 3;          // 0..3 : M slice (16 rows)
    int wn  = w >> 2;         // 0..1 : N slice (48 cols)

    // ---- loader slots (uint4 = 8 halves) ----
    // A: 64 rows x 64 k / 8 = 512 slots; 2 per thread
    int aR[2], aK[2];
#pragma unroll
    for (int s = 0; s < 2; s++) {
        int id = tid + s * GT;
        aR[s] = id >> 3; aK[s] = (id & 7) * 8;
    }
    // B: 64 k x 96 / 8 = 768 slots; 3 per thread
    int bR[3], bN[3];
#pragma unroll
    for (int s = 0; s < 3; s++) {
        int id = tid + s * GT;
        bR[s] = id / 12; bN[s] = (id % 12) * 8;
    }

    wmma::fragment<wmma::accumulator, 16, 16, 16, float> acc[3];
#pragma unroll
    for (int j = 0; j < 3; j++) wmma::fill_fragment(acc[j], 0.0f);

    // ---- initial global loads (k0 = 0) ----
    uint4 ra[2], rb[3];
#pragma unroll
    for (int s = 0; s < 2; s++)
        ra[s] = *(const uint4*)&Ad[(size_t)(rowBase + aR[s]) * LN + aK[s]];
#pragma unroll
    for (int s = 0; s < 3; s++)
        rb[s] = *(const uint4*)&Bd[(size_t)bR[s] * DD + colBase + bN[s]];

    int buf = 0;
    for (int k0 = 0; k0 < LN; k0 += GBK) {
#pragma unroll
        for (int s = 0; s < 2; s++)
            *(uint4*)&As[buf][aR[s]][aK[s]] = ra[s];
#pragma unroll
        for (int s = 0; s < 3; s++)
            *(uint4*)&Bs[buf][bR[s]][bN[s]] = rb[s];
        __syncthreads();

        int kn = k0 + GBK;
        if (kn < LN) {
#pragma unroll
            for (int s = 0; s < 2; s++)
                ra[s] = *(const uint4*)&Ad[(size_t)(rowBase + aR[s]) * LN + kn + aK[s]];
#pragma unroll
            for (int s = 0; s < 3; s++)
                rb[s] = *(const uint4*)&Bd[(size_t)(kn + bR[s]) * DD + colBase + bN[s]];
        }

#pragma unroll
        for (int kk = 0; kk < GBK / 16; kk++) {
            wmma::fragment<wmma::matrix_a, 16, 16, 16, __half, wmma::row_major> fa;
            wmma::fragment<wmma::matrix_b, 16, 16, 16, __half, wmma::row_major> fb[3];
            wmma::load_matrix_sync(fa, &As[buf][wm * 16][kk * 16], LDA);
#pragma unroll
            for (int j = 0; j < 3; j++)
                wmma::load_matrix_sync(fb[j], &Bs[buf][kk * 16][wn * 48 + j * 16], LDB);
#pragma unroll
            for (int j = 0; j < 3; j++)
                wmma::mma_sync(acc[j], fa, fb[j], acc[j]);
        }
        buf ^= 1;
        __syncthreads();
    }

    // ---- epilogue: store accumulators ----
#pragma unroll
    for (int j = 0; j < 3; j++) {
        float* c = &Cd[(size_t)(rowBase + wm * 16) * DD + colBase + wn * 48 + j * 16];
        wmma::store_matrix_sync(c, acc[j], DD, wmma::mem_row_major);
    }

    // ---- fused hs/ts plane copy for this block's (row, col) tile ----
    {
        const float4* emb4 = (const float4*)g_e_emb;
        float4* out4 = (float4*)out;
        size_t P4 = (size_t)n * RR * (DD / 4);
        // tile = 64 rows x 24 float4 cols = 1536 float4 per plane; 6 per thread
#pragma unroll
        for (int s = 0; s < 6; s++) {
            int idx = tid + s * GT;        // 0..1535
            int row = idx / 24;            // 0..63
            int c4  = idx % 24;
            int b = i * RR + rowBase + row;
            int ha = hts[b * 2 + 0];
            int ta = hts[b * 2 + 1];
            int col4 = colBase / 4 + c4;
            float4 vh = emb4[(size_t)(i * EE + ha) * (DD / 4) + col4];
            float4 vt = emb4[(size_t)(i * EE + ta) * (DD / 4) + col4];
            out4[(size_t)b * (DD / 4) + col4]      = vh;
            out4[P4 + (size_t)b * (DD / 4) + col4] = vt;
        }
    }
}

// ---------------------------------------------------------------------------
extern "C" void kernel_launch(void* const* d_in, const int* in_sizes, int n_in,
                              void* d_out, int out_size)
{
    const float* seq  = (const float*)d_in[0];   // (n, L, d)
    const float* att  = (const float*)d_in[1];   // (n, h, L, L)
    const int*   pos  = (const int*)  d_in[2];   // (n, E, M)
    const float* mask = (const float*)d_in[3];   // (n, E, M)
    const int*   hts  = (const int*)  d_in[4];   // (n, R, 2)
    float* out = (float*)d_out;

    int n = in_sizes[0] / (LN * DD);
    if (n > NMAX) n = NMAX;

    {   // fused e_emb + seq->fp16 + e_att(fp16)
        k_pre<<<NB_EMB + NB_SPL + NB_EATT, 256>>>(seq, att, pos, mask, n);
    }
    {   // ht_att (fp16 in, fp16 A out)
        k_ht_att<<<n * RR, 256>>>(hts, n);
    }
    {   // rs plane GEMM (single-term fp16, BK=64) + hs/ts copy
        dim3 grid(DD / GBN, RR / GBM, n);
        k_gemm<<<grid, GT>>>(hts, out, n);
    }
}

// round 15
// speedup vs baseline: 1.4917x; 1.0651x over previous
#include <cuda_runtime.h>
#include <cuda_fp16.h>
#include <mma.h>
#include <float.h>

using namespace nvcuda;

// Problem constants (fixed by reference setup_inputs)
#define LN   1024      // sequence length L
#define DD   768       // hidden d
#define HH   12        // heads
#define EE   32        // entities
#define MM   4         // mentions
#define RR   256       // relations per doc
#define NMAX 4         // batch

// Scratch (device globals -- no allocation allowed)
__device__ float g_e_emb[NMAX * EE * DD];                        // (n,E,d)
__device__ __align__(16) __half g_e_att[NMAX * EE * HH * LN];    // (n,E,h,L) fp16
__device__ __align__(16) __half g_A[NMAX * RR * LN];             // ht_att fp16
__device__ __align__(16) __half g_B[NMAX * LN * DD];             // seq fp16

// ---------------------------------------------------------------------------
// Kernel 1: e_att only — the big attention gather (latency/DRAM bound).
// 2 float4 per thread.
// ---------------------------------------------------------------------------
#define NB_EATT  ((NMAX * EE * HH * (LN / 4)) / 2 / 256)    // 768

__global__ void k_eatt(const float* __restrict__ att,
                       const int*   __restrict__ pos,
                       const float* __restrict__ mask,
                       int n)
{
    int half_n = n * EE * HH * (LN / 4) / 2;
    int base = blockIdx.x * 256 + threadIdx.x;
    if (base >= half_n) return;
#pragma unroll
    for (int u = 0; u < 2; u++) {
        int idx = base + u * half_n;
        int l4 = idx % (LN / 4);
        int hh = (idx / (LN / 4)) % HH;
        int e  = (idx / ((LN / 4) * HH)) % EE;
        int i  = idx / ((LN / 4) * HH * EE);
        const int4   p4 = *(const int4*)  (pos  + (i * EE + e) * MM);
        const float4 m4 = *(const float4*)(mask + (i * EE + e) * MM);
        const float4* att4 = (const float4*)att;
        int   pp[MM] = {p4.x + 1, p4.y + 1, p4.z + 1, p4.w + 1};
        float mk[MM] = {m4.x, m4.y, m4.z, m4.w};
        float cnt = mk[0] + mk[1] + mk[2] + mk[3];
        float4 s = make_float4(0.f, 0.f, 0.f, 0.f);
#pragma unroll
        for (int m = 0; m < MM; m++) {
            float4 a = att4[((size_t)(i * HH + hh) * LN + pp[m]) * (LN / 4) + l4];
            s.x += mk[m] * a.x; s.y += mk[m] * a.y;
            s.z += mk[m] * a.z; s.w += mk[m] * a.w;
        }
        float inv = 1.0f / fmaxf(cnt, 1.0f);
        __half2 h01 = __floats2half2_rn(s.x * inv, s.y * inv);
        __half2 h23 = __floats2half2_rn(s.z * inv, s.w * inv);
        uint2 w;
        w.x = *(unsigned*)&h01;
        w.y = *(unsigned*)&h23;
        ((uint2*)g_e_att)[idx] = w;
    }
}

// ---------------------------------------------------------------------------
// Kernel 2: ht_att (L2-bound) || seq->fp16 split (DRAM-bound) || e_emb
// (tiny gather) — disjoint resources run concurrently.
// Block ranges: [0, NB_HT) ht_att | [NB_HT, +NB_SPL) split | rest e_emb.
// ---------------------------------------------------------------------------
#define NB_HT    (NMAX * RR)                                // 1024
#define NB_SPL   ((NMAX * LN * DD / 4) / 2 / 256)           // 1536
#define NB_EMB   ((NMAX * EE * DD) / 256)                   // 384

__global__ void k_mid(const float* __restrict__ seq,
                      const int*   __restrict__ pos,
                      const float* __restrict__ mask,
                      const int*   __restrict__ hts,
                      int n)
{
    int blk = blockIdx.x;
    int t = threadIdx.x;
    if (blk < NB_HT) {
        // ---- ht_att: one block per (i,r) ----
        int b = blk;
        int i = b / RR;
        if (i >= n) return;
        int ha = hts[b * 2 + 0];
        int ta = hts[b * 2 + 1];

        const uint2* A = (const uint2*)(g_e_att + (size_t)(i * EE + ha) * HH * LN);
        const uint2* B = (const uint2*)(g_e_att + (size_t)(i * EE + ta) * HH * LN);

        float4 s = make_float4(0.f, 0.f, 0.f, 0.f);
#pragma unroll
        for (int hh = 0; hh < HH; hh++) {
            uint2 ua = A[hh * (LN / 4) + t];
            uint2 ub = B[hh * (LN / 4) + t];
            float2 a01 = __half22float2(*(__half2*)&ua.x);
            float2 a23 = __half22float2(*(__half2*)&ua.y);
            float2 b01 = __half22float2(*(__half2*)&ub.x);
            float2 b23 = __half22float2(*(__half2*)&ub.y);
            s.x += a01.x * b01.x; s.y += a01.y * b01.y;
            s.z += a23.x * b23.x; s.w += a23.y * b23.y;
        }
        const float invH = 1.0f / (float)HH;
        s.x *= invH; s.y *= invH; s.z *= invH; s.w *= invH;
        float local = s.x + s.y + s.z + s.w;

        __shared__ float red[8];
#pragma unroll
        for (int off = 16; off > 0; off >>= 1)
            local += __shfl_xor_sync(0xffffffffu, local, off);
        if ((t & 31) == 0) red[t >> 5] = local;
        __syncthreads();
        if (t < 32) {
            float x = (t < 8) ? red[t] : 0.0f;
#pragma unroll
            for (int off = 4; off > 0; off >>= 1)
                x += __shfl_xor_sync(0xffffffffu, x, off);
            if (t == 0) red[0] = x;
        }
        __syncthreads();
        float inv = 1.0f / (red[0] + 1e-5f);

        __half2 h01 = __floats2half2_rn(s.x * inv, s.y * inv);
        __half2 h23 = __floats2half2_rn(s.z * inv, s.w * inv);
        uint2 w;
        w.x = *(unsigned*)&h01;
        w.y = *(unsigned*)&h23;
        ((uint2*)(g_A + (size_t)b * LN))[t] = w;
    } else if (blk < NB_HT + NB_SPL) {
        // ---- seq -> fp16 (2 float4 per thread) ----
        int half_n = n * LN * DD / 4 / 2;
        int idx = (blk - NB_HT) * 256 + t;
        if (idx >= half_n) return;
#pragma unroll
        for (int u = 0; u < 2; u++) {
            int id = idx + u * half_n;
            float4 v = ((const float4*)seq)[id];
            __half2 h01 = __floats2half2_rn(v.x, v.y);
            __half2 h23 = __floats2half2_rn(v.z, v.w);
            uint2 w;
            w.x = *(unsigned*)&h01;
            w.y = *(unsigned*)&h23;
            ((uint2*)g_B)[id] = w;
        }
    } else {
        // ---- e_emb ----
        int idx = (blk - NB_HT - NB_SPL) * 256 + t;
        int total = n * EE * DD;
        if (idx >= total) return;
        int k = idx % DD;
        int e = (idx / DD) % EE;
        int i = idx / (DD * EE);
        const int*   p  = pos  + (i * EE + e) * MM;
        const float* mk = mask + (i * EE + e) * MM;
        float v[MM];
        float mx = -FLT_MAX;
#pragma unroll
        for (int m = 0; m < MM; m++) {
            int pp = p[m] + 1;                       // OFFSET
            float x = seq[(i * LN + pp) * DD + k];
            if (mk[m] <= 0.0f) x = -FLT_MAX;
            v[m] = x;
            mx = fmaxf(mx, x);
        }
        float s = 0.0f;
#pragma unroll
        for (int m = 0; m < MM; m++) s += expf(v[m] - mx);
        g_e_emb[idx] = mx + logf(s);
    }
}

// ---------------------------------------------------------------------------
// Kernel 3: rs plane GEMM, plain fp16 x fp16 -> fp32 (R14 proven config).
// Block 64x96, BK=64, 8 warps 4(M)x2(N), warp tile 16x48 (3 accs).
// Double-buffered smem, register prefetch. grid = 8x4x4 = 128 blocks.
// Fused hs/ts plane copy.
// ---------------------------------------------------------------------------
#define GBM 64
#define GBN 96
#define GBK 64
#define GT  256
#define LDA (GBK + 8)    // 72 halves
#define LDB (GBN + 8)    // 104 halves

__global__ __launch_bounds__(GT, 1) void k_gemm(const int* __restrict__ hts,
                                                float* __restrict__ out, int n)
{
    __shared__ __align__(16) __half As[2][GBM][LDA];
    __shared__ __align__(16) __half Bs[2][GBK][LDB];

    int i = blockIdx.z;
    const __half* Ad = g_A + (size_t)i * RR * LN;
    const __half* Bd = g_B + (size_t)i * LN * DD;
    size_t P = (size_t)n * RR * DD;
    float* Cd = out + 2 * P + (size_t)i * RR * DD;      // R x D

    int rowBase = blockIdx.y * GBM;
    int colBase = blockIdx.x * GBN;
    int tid = threadIdx.x;
    int w   = tid >> 5;
    int wm  = w & 3;          // 0..3 : M slice (16 rows)
    int wn  = w >> 2;         // 0..1 : N slice (48 cols)

    // ---- loader slots (uint4 = 8 halves) ----
    int aR[2], aK[2];
#pragma unroll
    for (int s = 0; s < 2; s++) {
        int id = tid + s * GT;
        aR[s] = id >> 3; aK[s] = (id & 7) * 8;
    }
    int bR[3], bN[3];
#pragma unroll
    for (int s = 0; s < 3; s++) {
        int id = tid + s * GT;
        bR[s] = id / 12; bN[s] = (id % 12) * 8;
    }

    wmma::fragment<wmma::accumulator, 16, 16, 16, float> acc[3];
#pragma unroll
    for (int j = 0; j < 3; j++) wmma::fill_fragment(acc[j], 0.0f);

    uint4 ra[2], rb[3];
#pragma unroll
    for (int s = 0; s < 2; s++)
        ra[s] = *(const uint4*)&Ad[(size_t)(rowBase + aR[s]) * LN + aK[s]];
#pragma unroll
    for (int s = 0; s < 3; s++)
        rb[s] = *(const uint4*)&Bd[(size_t)bR[s] * DD + colBase + bN[s]];

    int buf = 0;
    for (int k0 = 0; k0 < LN; k0 += GBK) {
#pragma unroll
        for (int s = 0; s < 2; s++)
            *(uint4*)&As[buf][aR[s]][aK[s]] = ra[s];
#pragma unroll
        for (int s = 0; s < 3; s++)
            *(uint4*)&Bs[buf][bR[s]][bN[s]] = rb[s];
        __syncthreads();

        int kn = k0 + GBK;
        if (kn < LN) {
#pragma unroll
            for (int s = 0; s < 2; s++)
                ra[s] = *(const uint4*)&Ad[(size_t)(rowBase + aR[s]) * LN + kn + aK[s]];
#pragma unroll
            for (int s = 0; s < 3; s++)
                rb[s] = *(const uint4*)&Bd[(size_t)(kn + bR[s]) * DD + colBase + bN[s]];
        }

#pragma unroll
        for (int kk = 0; kk < GBK / 16; kk++) {
            wmma::fragment<wmma::matrix_a, 16, 16, 16, __half, wmma::row_major> fa;
            wmma::fragment<wmma::matrix_b, 16, 16, 16, __half, wmma::row_major> fb[3];
            wmma::load_matrix_sync(fa, &As[buf][wm * 16][kk * 16], LDA);
#pragma unroll
            for (int j = 0; j < 3; j++)
                wmma::load_matrix_sync(fb[j], &Bs[buf][kk * 16][wn * 48 + j * 16], LDB);
#pragma unroll
            for (int j = 0; j < 3; j++)
                wmma::mma_sync(acc[j], fa, fb[j], acc[j]);
        }
        buf ^= 1;
        __syncthreads();
    }

#pragma unroll
    for (int j = 0; j < 3; j++) {
        float* c = &Cd[(size_t)(rowBase + wm * 16) * DD + colBase + wn * 48 + j * 16];
        wmma::store_matrix_sync(c, acc[j], DD, wmma::mem_row_major);
    }

    // ---- fused hs/ts plane copy for this block's (row, col) tile ----
    {
        const float4* emb4 = (const float4*)g_e_emb;
        float4* out4 = (float4*)out;
        size_t P4 = (size_t)n * RR * (DD / 4);
#pragma unroll
        for (int s = 0; s < 6; s++) {
            int idx = tid + s * GT;        // 0..1535
            int row = idx / 24;            // 0..63
            int c4  = idx % 24;
            int b = i * RR + rowBase + row;
            int ha = hts[b * 2 + 0];
            int ta = hts[b * 2 + 1];
            int col4 = colBase / 4 + c4;
            float4 vh = emb4[(size_t)(i * EE + ha) * (DD / 4) + col4];
            float4 vt = emb4[(size_t)(i * EE + ta) * (DD / 4) + col4];
            out4[(size_t)b * (DD / 4) + col4]      = vh;
            out4[P4 + (size_t)b * (DD / 4) + col4] = vt;
        }
    }
}

// ---------------------------------------------------------------------------
extern "C" void kernel_launch(void* const* d_in, const int* in_sizes, int n_in,
                              void* d_out, int out_size)
{
    const float* seq  = (const float*)d_in[0];   // (n, L, d)
    const float* att  = (const float*)d_in[1];   // (n, h, L, L)
    const int*   pos  = (const int*)  d_in[2];   // (n, E, M)
    const float* mask = (const float*)d_in[3];   // (n, E, M)
    const int*   hts  = (const int*)  d_in[4];   // (n, R, 2)
    float* out = (float*)d_out;

    int n = in_sizes[0] / (LN * DD);
    if (n > NMAX) n = NMAX;

    {   // k1: e_att gather
        k_eatt<<<NB_EATT, 256>>>(att, pos, mask, n);
    }
    {   // k2: ht_att || seq->fp16 || e_emb
        k_mid<<<NB_HT + NB_SPL + NB_EMB, 256>>>(seq, pos, mask, hts, n);
    }
    {   // k3: rs plane GEMM + hs/ts copy
        dim3 grid(DD / GBN, RR / GBM, n);
        k_gemm<<<grid, GT>>>(hts, out, n);
    }
}